// round 12
// baseline (speedup 1.0000x reference)
#include <cuda_runtime.h>

// DfOp: out[b,t,f] = sum_{i=0..4} spec[b, t+i-4, f] * coefs[b, i, t, f] (complex) for f < 96
//       out[b,t,f] = spec[b,t,f]                                                 for f >= 96
// spec:  (8, 1, 4096, 481, 2) f32, coefs: (8, 5, 4096, 96, 2) f32
//
// Block = 160 threads, persistent over CHUNK=8 consecutive virtual row-pairs.
// Virtual pair vb: par = vb&1, rows {4*(vb>>1)+par, +2} (same parity -> compile-time
// alignment via template<PAR>). Consecutive vb in one block => filter tap window
// (~3KB of spec history) stays resident in this SM's L1 across iterations.
//  tid 0..95   : filter, 2 bins/thread (5x LDG.128 coef + mixed spec loads)
//  tid 96..127 : copy float region [192,962) of row A (6x LDG.128)
//  tid 128..159: copy float region [192,962) of row B (6x LDG.128)

#define DF_B  8
#define DF_T  4096
#define DF_F  481
#define DF_NF 96
#define DF_FS 5
#define ROW_FLOATS (2 * DF_F)   // 962
#define CHUNK 8

template<int PAR>
__device__ __forceinline__ void do_filter(
    const float* __restrict__ specf,
    const float4* __restrict__ coefs4,
    float* __restrict__ outf,
    int row, int j)
{
    const int t = row & (DF_T - 1);
    const int b = row >> 12;
    const long rowf = (long)row * ROW_FLOATS;
    const int cbase = ((b * DF_FS) * DF_T + t) * 48 + j;
    const float* __restrict__ sp = specf + rowf + 4 * j;

    float re0 = 0.f, im0 = 0.f, re1 = 0.f, im1 = 0.f;
    if (t >= DF_FS - 1) {
        #pragma unroll
        for (int i = 0; i < DF_FS; i++) {
            float4 c = __ldcs(coefs4 + cbase + i * (DF_T * 48));
            const float* s = sp + (long)(i - (DF_FS - 1)) * ROW_FLOATS;
            float2 sa, sb;
            if (((i ^ PAR) & 1) == 0) {
                // tap base 16B-aligned: one LDG.128 covers both bins
                float4 v = *(const float4*)s;
                sa = make_float2(v.x, v.y);
                sb = make_float2(v.z, v.w);
            } else {
                sa = *(const float2*)s;
                sb = *(const float2*)(s + 2);
            }
            re0 = fmaf( sa.x, c.x, re0); re0 = fmaf(-sa.y, c.y, re0);
            im0 = fmaf( sa.x, c.y, im0); im0 = fmaf( sa.y, c.x, im0);
            re1 = fmaf( sb.x, c.z, re1); re1 = fmaf(-sb.y, c.w, re1);
            im1 = fmaf( sb.x, c.w, im1); im1 = fmaf( sb.y, c.z, im1);
        }
    } else {
        #pragma unroll
        for (int i = 0; i < DF_FS; i++) {
            if (t + i >= DF_FS - 1) {
                float4 c = __ldcs(coefs4 + cbase + i * (DF_T * 48));
                const float* s = sp + (long)(i - (DF_FS - 1)) * ROW_FLOATS;
                float2 sa = *(const float2*)(s);
                float2 sb = *(const float2*)(s + 2);
                re0 = fmaf( sa.x, c.x, re0); re0 = fmaf(-sa.y, c.y, re0);
                im0 = fmaf( sa.x, c.y, im0); im0 = fmaf( sa.y, c.x, im0);
                re1 = fmaf( sb.x, c.z, re1); re1 = fmaf(-sb.y, c.w, re1);
                im1 = fmaf( sb.x, c.w, im1); im1 = fmaf( sb.y, c.z, im1);
            }
        }
    }
    if (PAR == 0) {
        __stcs((float4*)(outf + rowf + 4 * j), make_float4(re0, im0, re1, im1));
    } else {
        __stcs((float2*)(outf + rowf + 4 * j),     make_float2(re0, im0));
        __stcs((float2*)(outf + rowf + 4 * j + 2), make_float2(re1, im1));
    }
}

__global__ __launch_bounds__(160) void df_op_kernel(
    const float* __restrict__ specf,
    const float4* __restrict__ coefs4,
    float* __restrict__ outf)
{
    const int tid = threadIdx.x;
    const int vb0 = blockIdx.x * CHUNK;

    #pragma unroll 1
    for (int it = 0; it < CHUNK; it++) {
        const int vb   = vb0 + it;
        const int par  = vb & 1;
        const int base = ((vb >> 1) << 2) + par;   // rows: base, base+2 (same parity)

        if (tid < 96) {
            const int row = base + ((tid >= 48) ? 2 : 0);
            const int j   = (tid >= 48) ? tid - 48 : tid;   // bins 2j, 2j+1
            if (par == 0) do_filter<0>(specf, coefs4, outf, row, j);
            else          do_filter<1>(specf, coefs4, outf, row, j);
        } else {
            // ---------------- copy path: one row per warp ----------------
            const int  w     = (tid - 96) >> 5;             // 0 -> base, 1 -> base+2
            const int  j     = tid & 31;                    // 0..31
            const long rf    = (long)(base + 2 * w) * ROW_FLOATS;
            const int  start = 192 + 2 * par;               // 16B-aligned float4 base

            const float4* __restrict__ s = (const float4*)(specf + rf + start);
            float4* __restrict__       d = (float4*)(outf + rf + start);

            float4 a0 = __ldcs(s + j);
            float4 a1 = __ldcs(s + j + 32);
            float4 a2 = __ldcs(s + j + 64);
            float4 a3 = __ldcs(s + j + 96);
            float4 a4 = __ldcs(s + j + 128);
            float4 a5 = __ldcs(s + j + 160);

            __stcs(d + j,       a0);
            __stcs(d + j + 32,  a1);
            __stcs(d + j + 64,  a2);
            __stcs(d + j + 96,  a3);
            __stcs(d + j + 128, a4);
            __stcs(d + j + 160, a5);

            // leftover float2: even rows at +960, odd rows at +192
            if (j == 0) {
                const long off = rf + (par ? 192 : 960);
                __stcs((float2*)(outf + off), __ldcs((const float2*)(specf + off)));
            }
        }
    }
}

extern "C" void kernel_launch(void* const* d_in, const int* in_sizes, int n_in,
                              void* d_out, int out_size)
{
    const float*  spec   = (const float*)d_in[0];
    const float4* coefs4 = (const float4*)d_in[1];
    float* out = (float*)d_out;

    df_op_kernel<<<(DF_B * DF_T) / 2 / CHUNK, 160>>>(spec, coefs4, out);
}

// round 14
// speedup vs baseline: 1.0817x; 1.0817x over previous
#include <cuda_runtime.h>

// DfOp: out[b,t,f] = sum_{i=0..4} spec[b, t+i-4, f] * coefs[b, i, t, f] (complex) for f < 96
//       out[b,t,f] = spec[b,t,f]                                                 for f >= 96
// spec:  (8, 1, 4096, 481, 2) f32, coefs: (8, 5, 4096, 96, 2) f32
//
// Block = 128 threads, TWO rows of the SAME parity: {4k,4k+2} (even bid) or
// {4k+1,4k+3} (odd bid). Parity block-uniform -> compile-time alignment.
// Warp-balanced split (~6-7 KB r+w per warp):
//  tid 0..95  : filter 2 bins of one row (5x LDG.128 coef + mixed spec loads)
//               PLUS copy 2 float4s of row A's [192,962) region (j=tid, tid+96)
//  tid 96..127: copy row B's [192,962) region entirely (6x LDG.128 / thread)
//               + the two leftover float2s

#define DF_B  8
#define DF_T  4096
#define DF_F  481
#define DF_NF 96
#define DF_FS 5
#define ROW_FLOATS (2 * DF_F)   // 962

template<int PAR>
__device__ __forceinline__ void do_filter(
    const float* __restrict__ specf,
    const float4* __restrict__ coefs4,
    float* __restrict__ outf,
    int row, int j)
{
    const int t = row & (DF_T - 1);
    const int b = row >> 12;
    const long rowf = (long)row * ROW_FLOATS;
    const int cbase = ((b * DF_FS) * DF_T + t) * 48 + j;
    const float* __restrict__ sp = specf + rowf + 4 * j;

    float re0 = 0.f, im0 = 0.f, re1 = 0.f, im1 = 0.f;
    if (t >= DF_FS - 1) {
        #pragma unroll
        for (int i = 0; i < DF_FS; i++) {
            float4 c = __ldcs(coefs4 + cbase + i * (DF_T * 48));
            const float* s = sp + (long)(i - (DF_FS - 1)) * ROW_FLOATS;
            float2 sa, sb;
            if (((i ^ PAR) & 1) == 0) {
                // tap base 16B-aligned: one LDG.128 covers both bins
                float4 v = *(const float4*)s;
                sa = make_float2(v.x, v.y);
                sb = make_float2(v.z, v.w);
            } else {
                sa = *(const float2*)s;
                sb = *(const float2*)(s + 2);
            }
            re0 = fmaf( sa.x, c.x, re0); re0 = fmaf(-sa.y, c.y, re0);
            im0 = fmaf( sa.x, c.y, im0); im0 = fmaf( sa.y, c.x, im0);
            re1 = fmaf( sb.x, c.z, re1); re1 = fmaf(-sb.y, c.w, re1);
            im1 = fmaf( sb.x, c.w, im1); im1 = fmaf( sb.y, c.z, im1);
        }
    } else {
        #pragma unroll
        for (int i = 0; i < DF_FS; i++) {
            if (t + i >= DF_FS - 1) {
                float4 c = __ldcs(coefs4 + cbase + i * (DF_T * 48));
                const float* s = sp + (long)(i - (DF_FS - 1)) * ROW_FLOATS;
                float2 sa = *(const float2*)(s);
                float2 sb = *(const float2*)(s + 2);
                re0 = fmaf( sa.x, c.x, re0); re0 = fmaf(-sa.y, c.y, re0);
                im0 = fmaf( sa.x, c.y, im0); im0 = fmaf( sa.y, c.x, im0);
                re1 = fmaf( sb.x, c.z, re1); re1 = fmaf(-sb.y, c.w, re1);
                im1 = fmaf( sb.x, c.w, im1); im1 = fmaf( sb.y, c.z, im1);
            }
        }
    }
    if (PAR == 0) {
        // output base 16B-aligned: single STG.128
        __stcs((float4*)(outf + rowf + 4 * j), make_float4(re0, im0, re1, im1));
    } else {
        __stcs((float2*)(outf + rowf + 4 * j),     make_float2(re0, im0));
        __stcs((float2*)(outf + rowf + 4 * j + 2), make_float2(re1, im1));
    }
}

__global__ __launch_bounds__(128) void df_op_kernel(
    const float* __restrict__ specf,
    const float4* __restrict__ coefs4,
    float* __restrict__ outf)
{
    const int bid  = blockIdx.x;
    const int par  = bid & 1;
    const int base = ((bid >> 1) << 2) + par;   // rows: base, base+2 (same parity)
    const int tid  = threadIdx.x;

    const int  start = 192 + 2 * par;           // 16B-aligned float4 base of copy region
    const long rfA   = (long)base * ROW_FLOATS;
    const long rfB   = rfA + 2 * ROW_FLOATS;

    if (tid < 96) {
        // ---- copy share: 2 float4s of row A (independent of filter, batches in) ----
        const float4* __restrict__ sA = (const float4*)(specf + rfA + start);
        float4* __restrict__       dA = (float4*)(outf + rfA + start);
        float4 ca = __ldcs(sA + tid);
        float4 cb = __ldcs(sA + tid + 96);

        // ---- filter: 2 bins of one row ----
        const int row = base + ((tid >= 48) ? 2 : 0);
        const int j   = (tid >= 48) ? tid - 48 : tid;   // 0..47 -> bins 2j, 2j+1
        if (par == 0) do_filter<0>(specf, coefs4, outf, row, j);
        else          do_filter<1>(specf, coefs4, outf, row, j);

        __stcs(dA + tid,      ca);
        __stcs(dA + tid + 96, cb);
    } else {
        // ---- copy path: row B entirely ----
        const int j = tid - 96;                         // 0..31
        const float4* __restrict__ s = (const float4*)(specf + rfB + start);
        float4* __restrict__       d = (float4*)(outf + rfB + start);

        float4 a0 = __ldcs(s + j);
        float4 a1 = __ldcs(s + j + 32);
        float4 a2 = __ldcs(s + j + 64);
        float4 a3 = __ldcs(s + j + 96);
        float4 a4 = __ldcs(s + j + 128);
        float4 a5 = __ldcs(s + j + 160);

        __stcs(d + j,       a0);
        __stcs(d + j + 32,  a1);
        __stcs(d + j + 64,  a2);
        __stcs(d + j + 96,  a3);
        __stcs(d + j + 128, a4);
        __stcs(d + j + 160, a5);

        // leftover float2s: even rows at +960, odd rows at +192
        if (j == 0) {
            const long off = rfA + (par ? 192 : 960);
            __stcs((float2*)(outf + off), __ldcs((const float2*)(specf + off)));
        } else if (j == 1) {
            const long off = rfB + (par ? 192 : 960);
            __stcs((float2*)(outf + off), __ldcs((const float2*)(specf + off)));
        }
    }
}

extern "C" void kernel_launch(void* const* d_in, const int* in_sizes, int n_in,
                              void* d_out, int out_size)
{
    const float*  spec   = (const float*)d_in[0];
    const float4* coefs4 = (const float4*)d_in[1];
    float* out = (float*)d_out;

    df_op_kernel<<<(DF_B * DF_T) / 2, 128>>>(spec, coefs4, out);
}

// round 17
// speedup vs baseline: 1.0893x; 1.0070x over previous
#include <cuda_runtime.h>

// DfOp: out[b,t,f] = sum_{i=0..4} spec[b, t+i-4, f] * coefs[b, i, t, f] (complex) for f < 96
//       out[b,t,f] = spec[b,t,f]                                                 for f >= 96
// spec:  (8, 1, 4096, 481, 2) f32, coefs: (8, 5, 4096, 96, 2) f32
//
// Block = 192 threads, TWO rows of the SAME parity: {4k,4k+2} (even bid) or
// {4k+1,4k+3} (odd bid). Parity block-uniform -> compile-time alignment.
//  tid 0..95   : filter, 2 bins/thread (5x LDG.128 coef + mixed spec loads)
//  tid 96..191 : copy float region [192,962) of BOTH rows; thread c copies
//                float4s {c, c+96} of row A and {c, c+96} of row B
//                (4x LDG.128, every instruction warp-contiguous)

#define DF_B  8
#define DF_T  4096
#define DF_F  481
#define DF_NF 96
#define DF_FS 5
#define ROW_FLOATS (2 * DF_F)   // 962

template<int PAR>
__device__ __forceinline__ void do_filter(
    const float* __restrict__ specf,
    const float4* __restrict__ coefs4,
    float* __restrict__ outf,
    int row, int j)
{
    const int t = row & (DF_T - 1);
    const int b = row >> 12;
    const long rowf = (long)row * ROW_FLOATS;
    const int cbase = ((b * DF_FS) * DF_T + t) * 48 + j;
    const float* __restrict__ sp = specf + rowf + 4 * j;

    float re0 = 0.f, im0 = 0.f, re1 = 0.f, im1 = 0.f;
    if (t >= DF_FS - 1) {
        #pragma unroll
        for (int i = 0; i < DF_FS; i++) {
            float4 c = __ldcs(coefs4 + cbase + i * (DF_T * 48));
            const float* s = sp + (long)(i - (DF_FS - 1)) * ROW_FLOATS;
            float2 sa, sb;
            if (((i ^ PAR) & 1) == 0) {
                // tap base 16B-aligned: one LDG.128 covers both bins
                float4 v = *(const float4*)s;
                sa = make_float2(v.x, v.y);
                sb = make_float2(v.z, v.w);
            } else {
                sa = *(const float2*)s;
                sb = *(const float2*)(s + 2);
            }
            re0 = fmaf( sa.x, c.x, re0); re0 = fmaf(-sa.y, c.y, re0);
            im0 = fmaf( sa.x, c.y, im0); im0 = fmaf( sa.y, c.x, im0);
            re1 = fmaf( sb.x, c.z, re1); re1 = fmaf(-sb.y, c.w, re1);
            im1 = fmaf( sb.x, c.w, im1); im1 = fmaf( sb.y, c.z, im1);
        }
    } else {
        #pragma unroll
        for (int i = 0; i < DF_FS; i++) {
            if (t + i >= DF_FS - 1) {
                float4 c = __ldcs(coefs4 + cbase + i * (DF_T * 48));
                const float* s = sp + (long)(i - (DF_FS - 1)) * ROW_FLOATS;
                float2 sa = *(const float2*)(s);
                float2 sb = *(const float2*)(s + 2);
                re0 = fmaf( sa.x, c.x, re0); re0 = fmaf(-sa.y, c.y, re0);
                im0 = fmaf( sa.x, c.y, im0); im0 = fmaf( sa.y, c.x, im0);
                re1 = fmaf( sb.x, c.z, re1); re1 = fmaf(-sb.y, c.w, re1);
                im1 = fmaf( sb.x, c.w, im1); im1 = fmaf( sb.y, c.z, im1);
            }
        }
    }
    if (PAR == 0) {
        // output base 16B-aligned: single STG.128
        __stcs((float4*)(outf + rowf + 4 * j), make_float4(re0, im0, re1, im1));
    } else {
        __stcs((float2*)(outf + rowf + 4 * j),     make_float2(re0, im0));
        __stcs((float2*)(outf + rowf + 4 * j + 2), make_float2(re1, im1));
    }
}

__global__ __launch_bounds__(192) void df_op_kernel(
    const float* __restrict__ specf,
    const float4* __restrict__ coefs4,
    float* __restrict__ outf)
{
    const int bid  = blockIdx.x;
    const int par  = bid & 1;
    const int base = ((bid >> 1) << 2) + par;   // rows: base, base+2 (same parity)
    const int tid  = threadIdx.x;

    if (tid < 96) {
        const int row = base + ((tid >= 48) ? 2 : 0);
        const int j   = (tid >= 48) ? tid - 48 : tid;   // 0..47 -> bins 2j, 2j+1
        if (par == 0) do_filter<0>(specf, coefs4, outf, row, j);
        else          do_filter<1>(specf, coefs4, outf, row, j);
    } else {
        // ---------------- copy path: both rows, 4 float4s per thread ----------------
        const int  c     = tid - 96;                    // 0..95
        const long rfA   = (long)base * ROW_FLOATS;
        const long rfB   = rfA + 2 * ROW_FLOATS;
        const int  start = 192 + 2 * par;               // 16B-aligned float4 base

        const float4* __restrict__ sA = (const float4*)(specf + rfA + start);
        const float4* __restrict__ sB = (const float4*)(specf + rfB + start);
        float4* __restrict__ dA = (float4*)(outf + rfA + start);
        float4* __restrict__ dB = (float4*)(outf + rfB + start);

        // 4 front-batched LDG.128, all warp-contiguous
        float4 a0 = __ldcs(sA + c);
        float4 a1 = __ldcs(sA + c + 96);
        float4 b0 = __ldcs(sB + c);
        float4 b1 = __ldcs(sB + c + 96);

        __stcs(dA + c,      a0);
        __stcs(dA + c + 96, a1);
        __stcs(dB + c,      b0);
        __stcs(dB + c + 96, b1);

        // leftover float2s: even rows at +960, odd rows at +192
        if (c == 0) {
            const long off = rfA + (par ? 192 : 960);
            __stcs((float2*)(outf + off), __ldcs((const float2*)(specf + off)));
        } else if (c == 1) {
            const long off = rfB + (par ? 192 : 960);
            __stcs((float2*)(outf + off), __ldcs((const float2*)(specf + off)));
        }
    }
}

extern "C" void kernel_launch(void* const* d_in, const int* in_sizes, int n_in,
                              void* d_out, int out_size)
{
    const float*  spec   = (const float*)d_in[0];
    const float4* coefs4 = (const float4*)d_in[1];
    float* out = (float*)d_out;

    df_op_kernel<<<(DF_B * DF_T) / 2, 192>>>(spec, coefs4, out);
}